// round 12
// baseline (speedup 1.0000x reference)
#include <cuda_runtime.h>
#include <cuda_fp16.h>
#include <cstdint>
#include <math.h>

// ---------------- scratch (no allocations allowed; __device__ globals are the sanctioned path) ----
#define MAXROWS_TOTAL 220000               // 120000 + 100000
__device__ __align__(16) __half g_xh[(size_t)MAXROWS_TOTAL * 256];  // fp16 copy of x1|x2 (112.6MB)

__device__ __align__(16) float g_sum[2][256];    // pass-1: sum(x)
__device__ __align__(16) float g_sumax[2][256];  // pass-2: sum(att*x)
__device__ __align__(16) float g_outv[2][256];   // pass-3: graph embedding (one head)
__device__ __align__(16) float g_h1[2][256];
__device__ __align__(16) float g_h2[2][256];
__device__ float g_wacc[16];

__device__ __forceinline__ float sigf_fast(float z) { return 1.0f / (1.0f + __expf(-z)); }

static const int PGRID = 444;   // 148 SMs * 3 CTAs -> single wave
#define TILE_ROWS 16
#define TILE_F4   (TILE_ROWS * 64)        // 1024 float4 = 16 KB
#define STAGES    4
#define DYN_SMEM  (STAGES * TILE_F4 * 16) // 64 KB

// ---------------- zero accumulators ----------------
__global__ void k_zero() {
    int t = threadIdx.x;
    g_sum[0][t] = 0.f;  g_sum[1][t] = 0.f;
    g_sumax[0][t] = 0.f; g_sumax[1][t] = 0.f;
    g_outv[0][t] = 0.f;  g_outv[1][t] = 0.f;
    if (t < 16) g_wacc[t] = 0.f;
}

// ---------------- cp.async (evict_first on the fp32 stream) ----------------
__device__ __forceinline__ void stage_tile_ef(float4* dst, const float4* src, unsigned long long pol) {
    int t = threadIdx.x;
    unsigned int s = (unsigned int)__cvta_generic_to_shared(dst + t);
    const float4* g = src + t;
    #pragma unroll
    for (int i = 0; i < 4; ++i) {
        asm volatile("cp.async.cg.shared.global.L2::cache_hint [%0], [%1], 16, %2;"
                     :: "r"(s + i * 256 * 16), "l"(g + i * 256), "l"(pol));
    }
}
#define CP_COMMIT()  asm volatile("cp.async.commit_group;" ::: "memory")
#define CP_WAIT3()   asm volatile("cp.async.wait_group 3;" ::: "memory")

// ---------------- k_conv: fp32 -> (column sum, fp16 copy) ----------------
__global__ void __launch_bounds__(256) k_conv(const float4* __restrict__ x, int nrows, int g, int base_row) {
    extern __shared__ __align__(16) float4 buf[];
    __shared__ float bacc[256];
    int t = threadIdx.x;
    bacc[t] = 0.f;
    unsigned long long pol;
    asm("createpolicy.fractional.L2::evict_first.b64 %0, 1.0;" : "=l"(pol));

    int cg = t & 63, rp = t >> 6;
    float4 a4 = make_float4(0.f, 0.f, 0.f, 0.f);
    uint2* xh2 = (uint2*)g_xh;   // one uint2 = 4 halves, row stride 64 uint2

    int ntiles = nrows >> 4;
    #pragma unroll
    for (int j = 0; j < STAGES - 1; ++j) {
        int tl = blockIdx.x + j * gridDim.x;
        if (tl < ntiles) stage_tile_ef(buf + j * TILE_F4, x + (size_t)tl * TILE_F4, pol);
        CP_COMMIT();
    }
    int it = 0;
    for (int tile = blockIdx.x; tile < ntiles; tile += gridDim.x, ++it) {
        int nxt = tile + (STAGES - 1) * gridDim.x;
        if (nxt < ntiles) stage_tile_ef(buf + ((it + STAGES - 1) & (STAGES - 1)) * TILE_F4,
                                        x + (size_t)nxt * TILE_F4, pol);
        CP_COMMIT();
        CP_WAIT3();
        __syncthreads();
        const float4* bt = buf + (it & (STAGES - 1)) * TILE_F4;
        size_t row0 = (size_t)base_row + ((size_t)tile << 4);
        #pragma unroll
        for (int j = 0; j < 4; ++j) {
            int lr = rp + j * 4;
            float4 v = bt[lr * 64 + cg];
            a4.x += v.x; a4.y += v.y; a4.z += v.z; a4.w += v.w;
            __half2 h01 = __floats2half2_rn(v.x, v.y);
            __half2 h23 = __floats2half2_rn(v.z, v.w);
            uint2 st;
            st.x = *(unsigned int*)&h01;
            st.y = *(unsigned int*)&h23;
            xh2[(row0 + lr) * 64 + cg] = st;
        }
        __syncthreads();
    }
    // tail rows (none for 120000/100000, guarded anyway)
    int full = ntiles << 4;
    int rem = nrows - full;
    if (rem > 0) {
        int gt = blockIdx.x * 256 + t;
        int total = gridDim.x * 256;
        for (int idx = gt; idx < rem * 64; idx += total) {
            int r = full + (idx >> 6), c = idx & 63;
            float4 v = x[(size_t)r * 64 + c];
            __half2 h01 = __floats2half2_rn(v.x, v.y);
            __half2 h23 = __floats2half2_rn(v.z, v.w);
            uint2 st; st.x = *(unsigned int*)&h01; st.y = *(unsigned int*)&h23;
            xh2[((size_t)base_row + r) * 64 + c] = st;
            atomicAdd(&g_sum[g][4 * c + 0], v.x);
            atomicAdd(&g_sum[g][4 * c + 1], v.y);
            atomicAdd(&g_sum[g][4 * c + 2], v.z);
            atomicAdd(&g_sum[g][4 * c + 3], v.w);
        }
    }
    __syncthreads();
    atomicAdd(&bacc[4 * cg + 0], a4.x);
    atomicAdd(&bacc[4 * cg + 1], a4.y);
    atomicAdd(&bacc[4 * cg + 2], a4.z);
    atomicAdd(&bacc[4 * cg + 3], a4.w);
    __syncthreads();
    atomicAdd(&g_sum[g][t], bacc[t]);
}

// ---------------- tiny matvec: h = tanh((src/N) @ W0) ----------------
__global__ void __launch_bounds__(256) k_h(const float* __restrict__ W0, float invN, int g, int stage) {
    __shared__ float tv[256];
    __shared__ float part[8][33];
    int t = threadIdx.x;
    const float* src = stage ? g_sumax[g] : g_sum[g];
    tv[t] = src[t] * invN;
    __syncthreads();
    int w = t >> 5, l = t & 31;
    int j = blockIdx.x * 32 + l;
    float acc = 0.f;
    const float* col = W0 + (size_t)(w * 32) * 256 + j;
    #pragma unroll 8
    for (int i = 0; i < 32; ++i) acc = fmaf(tv[w * 32 + i], col[i * 256], acc);
    part[w][l] = acc;
    __syncthreads();
    if (w == 0) {
        float s = 0.f;
        #pragma unroll
        for (int k = 0; k < 8; ++k) s += part[k][l];
        float* dst = stage ? g_h2[g] : g_h1[g];
        dst[j] = tanhf(s);
    }
}

// unpack uint4 (8 halves) -> 8 floats
__device__ __forceinline__ void unpack8(uint4 u, float* f) {
    __half2 h;
    float2 p;
    h = *(__half2*)&u.x; p = __half22float2(h); f[0] = p.x; f[1] = p.y;
    h = *(__half2*)&u.y; p = __half22float2(h); f[2] = p.x; f[3] = p.y;
    h = *(__half2*)&u.z; p = __half22float2(h); f[4] = p.x; f[5] = p.y;
    h = *(__half2*)&u.w; p = __half22float2(h); f[6] = p.x; f[7] = p.y;
}

// block reduce for 8-cols-per-lane layout
__device__ __forceinline__ void block_reduce8(float* bacc, int t, int lane,
                                              const float* a, float* gdst) {
    __syncthreads();   // bacc zeroed at kernel start by all threads
    #pragma unroll
    for (int i = 0; i < 8; ++i) atomicAdd(&bacc[8 * lane + i], a[i]);
    __syncthreads();
    atomicAdd(&gdst[t], bacc[t]);
}

// ---------------- pass 2 (fp16): att = sigmoid(x.h1); sum(att*x) ----------------
__global__ void __launch_bounds__(256) k_att2(int nrows, int g, int base_row) {
    __shared__ float bacc[256];
    int t = threadIdx.x;
    bacc[t] = 0.f;
    int lane = t & 31;
    const uint4* xh = (const uint4*)g_xh + (size_t)base_row * 32;  // 32 uint4 per row
    float hv[8], a[8];
    #pragma unroll
    for (int i = 0; i < 8; ++i) { hv[i] = g_h1[g][8 * lane + i]; a[i] = 0.f; }

    int gw = (blockIdx.x << 3) + (t >> 5);
    int nW = gridDim.x << 3;
    int ngroups = nrows >> 2;
    for (int gi = gw; gi < ngroups; gi += nW) {
        const uint4* base = xh + ((size_t)gi << 7);  // 4 rows * 32
        uint4 u0 = base[lane], u1 = base[32 + lane], u2 = base[64 + lane], u3 = base[96 + lane];
        float f0[8], f1[8], f2[8], f3[8];
        unpack8(u0, f0); unpack8(u1, f1); unpack8(u2, f2); unpack8(u3, f3);
        float p0 = 0.f, p1 = 0.f, p2 = 0.f, p3 = 0.f;
        #pragma unroll
        for (int i = 0; i < 8; ++i) {
            p0 = fmaf(f0[i], hv[i], p0); p1 = fmaf(f1[i], hv[i], p1);
            p2 = fmaf(f2[i], hv[i], p2); p3 = fmaf(f3[i], hv[i], p3);
        }
        #pragma unroll
        for (int o = 16; o; o >>= 1) {
            p0 += __shfl_xor_sync(0xffffffffu, p0, o);
            p1 += __shfl_xor_sync(0xffffffffu, p1, o);
            p2 += __shfl_xor_sync(0xffffffffu, p2, o);
            p3 += __shfl_xor_sync(0xffffffffu, p3, o);
        }
        float t0 = sigf_fast(p0), t1 = sigf_fast(p1), t2 = sigf_fast(p2), t3 = sigf_fast(p3);
        #pragma unroll
        for (int i = 0; i < 8; ++i)
            a[i] += t0 * f0[i] + t1 * f1[i] + t2 * f2[i] + t3 * f3[i];
    }
    int full = ngroups << 2;
    int rem = nrows - full;
    if (gw < rem) {
        const uint4* base = xh + (size_t)(full + gw) * 32;
        uint4 u = base[lane];
        float f[8]; unpack8(u, f);
        float p = 0.f;
        #pragma unroll
        for (int i = 0; i < 8; ++i) p = fmaf(f[i], hv[i], p);
        #pragma unroll
        for (int o = 16; o; o >>= 1) p += __shfl_xor_sync(0xffffffffu, p, o);
        float att = sigf_fast(p);
        #pragma unroll
        for (int i = 0; i < 8; ++i) a[i] += att * f[i];
    }
    block_reduce8(bacc, t, lane, a, g_sumax[g]);
}

// ---------------- pass 3 (fp16): out = sum(sig(att*(x.h2))*att*x) ----------------
__global__ void __launch_bounds__(256) k_out2(int nrows, int g, int base_row) {
    __shared__ float bacc[256];
    int t = threadIdx.x;
    bacc[t] = 0.f;
    int lane = t & 31;
    const uint4* xh = (const uint4*)g_xh + (size_t)base_row * 32;
    float hv[8], gv[8], a[8];
    #pragma unroll
    for (int i = 0; i < 8; ++i) {
        hv[i] = g_h1[g][8 * lane + i];
        gv[i] = g_h2[g][8 * lane + i];
        a[i] = 0.f;
    }

    int gw = (blockIdx.x << 3) + (t >> 5);
    int nW = gridDim.x << 3;
    int ngroups = nrows >> 2;
    for (int gi = gw; gi < ngroups; gi += nW) {
        const uint4* base = xh + ((size_t)gi << 7);
        uint4 u0 = base[lane], u1 = base[32 + lane], u2 = base[64 + lane], u3 = base[96 + lane];
        float f0[8], f1[8], f2[8], f3[8];
        unpack8(u0, f0); unpack8(u1, f1); unpack8(u2, f2); unpack8(u3, f3);
        float p0 = 0.f, p1 = 0.f, p2 = 0.f, p3 = 0.f;
        float q0 = 0.f, q1 = 0.f, q2 = 0.f, q3 = 0.f;
        #pragma unroll
        for (int i = 0; i < 8; ++i) {
            p0 = fmaf(f0[i], hv[i], p0); p1 = fmaf(f1[i], hv[i], p1);
            p2 = fmaf(f2[i], hv[i], p2); p3 = fmaf(f3[i], hv[i], p3);
            q0 = fmaf(f0[i], gv[i], q0); q1 = fmaf(f1[i], gv[i], q1);
            q2 = fmaf(f2[i], gv[i], q2); q3 = fmaf(f3[i], gv[i], q3);
        }
        #pragma unroll
        for (int o = 16; o; o >>= 1) {
            p0 += __shfl_xor_sync(0xffffffffu, p0, o);
            p1 += __shfl_xor_sync(0xffffffffu, p1, o);
            p2 += __shfl_xor_sync(0xffffffffu, p2, o);
            p3 += __shfl_xor_sync(0xffffffffu, p3, o);
            q0 += __shfl_xor_sync(0xffffffffu, q0, o);
            q1 += __shfl_xor_sync(0xffffffffu, q1, o);
            q2 += __shfl_xor_sync(0xffffffffu, q2, o);
            q3 += __shfl_xor_sync(0xffffffffu, q3, o);
        }
        float t0 = sigf_fast(p0), t1 = sigf_fast(p1), t2 = sigf_fast(p2), t3 = sigf_fast(p3);
        t0 *= sigf_fast(t0 * q0);
        t1 *= sigf_fast(t1 * q1);
        t2 *= sigf_fast(t2 * q2);
        t3 *= sigf_fast(t3 * q3);
        #pragma unroll
        for (int i = 0; i < 8; ++i)
            a[i] += t0 * f0[i] + t1 * f1[i] + t2 * f2[i] + t3 * f3[i];
    }
    int full = ngroups << 2;
    int rem = nrows - full;
    if (gw < rem) {
        const uint4* base = xh + (size_t)(full + gw) * 32;
        uint4 u = base[lane];
        float f[8]; unpack8(u, f);
        float p = 0.f, q = 0.f;
        #pragma unroll
        for (int i = 0; i < 8; ++i) { p = fmaf(f[i], hv[i], p); q = fmaf(f[i], gv[i], q); }
        #pragma unroll
        for (int o = 16; o; o >>= 1) {
            p += __shfl_xor_sync(0xffffffffu, p, o);
            q += __shfl_xor_sync(0xffffffffu, q, o);
        }
        float att = sigf_fast(p);
        float wgt = att * sigf_fast(att * q);
        #pragma unroll
        for (int i = 0; i < 8; ++i) a[i] += wgt * f[i];
    }
    block_reduce8(bacc, t, lane, a, g_outv[g]);
}

// ---------------- NTN: w_term (streams W, 16.8MB) + v_term ----------------
__global__ void __launch_bounds__(256) k_ntn(const float* __restrict__ W, const float* __restrict__ V) {
    __shared__ float g1s[16];
    __shared__ float red[8];
    int b = blockIdx.x, t = threadIdx.x;
    float acc = 0.f;
    int f;
    if (b < 512) {
        f = b >> 5;
        int chunk = b & 31;
        if (t < 16) g1s[t] = g_outv[0][(chunk * 16 + t) & 255];
        __syncthreads();
        float o2 = g_outv[1][t];
        const float* base = W + ((size_t)f * 512 + chunk * 16) * 512;
        #pragma unroll
        for (int i = 0; i < 16; ++i) {
            const float* wr = base + (size_t)i * 512;
            acc += g1s[i] * (wr[t] + wr[t + 256]);
        }
        acc *= o2;
    } else {
        f = b - 512;
        const float* vf = V + (size_t)f * 1024;
        acc = g_outv[0][t] * (vf[t] + vf[256 + t])
            + g_outv[1][t] * (vf[512 + t] + vf[768 + t]);
    }
    #pragma unroll
    for (int o = 16; o; o >>= 1) acc += __shfl_xor_sync(0xffffffffu, acc, o);
    if ((t & 31) == 0) red[t >> 5] = acc;
    __syncthreads();
    if (t < 8) {
        float s = red[t];
        s += __shfl_xor_sync(0xffu, s, 4);
        s += __shfl_xor_sync(0xffu, s, 2);
        s += __shfl_xor_sync(0xffu, s, 1);
        if (t == 0) atomicAdd(&g_wacc[f], s);
    }
}

// ---------------- final: sigmoid(NTN) -> MLP 16->8->4->2->1 ----------------
__global__ void k_final(const float* __restrict__ b, const float* __restrict__ P0,
                        const float* __restrict__ P1, const float* __restrict__ P2,
                        const float* __restrict__ P3, float* __restrict__ out) {
    int t = threadIdx.x;
    __shared__ float s[16];
    if (t < 16) s[t] = 1.f / (1.f + expf(-(g_wacc[t] + b[t])));
    __syncwarp();
    if (t == 0) {
        float y0[8];
        #pragma unroll
        for (int o = 0; o < 8; ++o) {
            float a = 0.f;
            #pragma unroll
            for (int ff = 0; ff < 16; ++ff) a += s[ff] * P0[o * 16 + ff];
            y0[o] = 1.f / (1.f + expf(-a));
        }
        float y1[4];
        #pragma unroll
        for (int o = 0; o < 4; ++o) {
            float a = 0.f;
            #pragma unroll
            for (int ff = 0; ff < 8; ++ff) a += y0[ff] * P1[o * 8 + ff];
            y1[o] = 1.f / (1.f + expf(-a));
        }
        float y2[2];
        #pragma unroll
        for (int o = 0; o < 2; ++o) {
            float a = 0.f;
            #pragma unroll
            for (int ff = 0; ff < 4; ++ff) a += y1[ff] * P2[o * 4 + ff];
            y2[o] = 1.f / (1.f + expf(-a));
        }
        float a = y2[0] * P3[0] + y2[1] * P3[1];
        out[0] = 1.f / (1.f + expf(-a));
    }
}

extern "C" void kernel_launch(void* const* d_in, const int* in_sizes, int n_in,
                              void* d_out, int out_size) {
    const float* x1 = (const float*)d_in[0];
    const float* x2 = (const float*)d_in[1];
    const float* W0 = (const float*)d_in[2];
    const float* V  = (const float*)d_in[3];
    const float* W  = (const float*)d_in[4];
    const float* bb = (const float*)d_in[5];
    const float* P0 = (const float*)d_in[6];
    const float* P1 = (const float*)d_in[7];
    const float* P2 = (const float*)d_in[8];
    const float* P3 = (const float*)d_in[9];
    int N1 = in_sizes[0] / 256;
    int N2 = in_sizes[1] / 256;
    float* out = (float*)d_out;

    static int attr_done = 0;
    if (!attr_done) {
        cudaFuncSetAttribute(k_conv, cudaFuncAttributeMaxDynamicSharedMemorySize, DYN_SMEM);
        attr_done = 1;
    }

    k_zero<<<1, 256>>>();

    // pass 1 + fp16 conversion (both graphs back-to-back: halves land resident in L2)
    k_conv<<<PGRID, 256, DYN_SMEM>>>((const float4*)x1, N1, 0, 0);
    k_conv<<<PGRID, 256, DYN_SMEM>>>((const float4*)x2, N2, 1, N1);
    k_h   <<<8, 256>>>(W0, 1.f / (float)N1, 0, 0);
    k_h   <<<8, 256>>>(W0, 1.f / (float)N2, 1, 0);

    // pass 2 on fp16 (L2-hot)
    k_att2<<<PGRID, 256>>>(N1, 0, 0);
    k_att2<<<PGRID, 256>>>(N2, 1, N1);
    k_h   <<<8, 256>>>(W0, 1.f / (float)N1, 0, 1);
    k_h   <<<8, 256>>>(W0, 1.f / (float)N2, 1, 1);

    // pass 3 on fp16 (L2-hot)
    k_out2<<<PGRID, 256>>>(N1, 0, 0);
    k_out2<<<PGRID, 256>>>(N2, 1, N1);

    // NTN bilinear + v_term, then tiny MLP head
    k_ntn  <<<528, 256>>>(W, V);
    k_final<<<1, 32>>>(bb, P0, P1, P2, P3, out);
}